// round 6
// baseline (speedup 1.0000x reference)
#include <cuda_runtime.h>
#include <math.h>
#include <stdint.h>

// RVQE: 12-qubit real statevector recurrent cell, B=64, T=9 (8 scan steps).
// One CTA per batch element; state = 4096 floats = 512 threads x 8 registers.
// Global amplitude index g (12 bits), g = (t << 3) | r:
//   r bits (local):  bit0=lane11(anc1), bit1=lane10(anc0), bit2=lane9
//   t bits 0..4 (warp lane): lanes 8,7,6,5,4  -> __shfl_xor (mask 1<<(8-lane))
//   t bits 5..8  (warp id):  lanes 3,2,1,0    -> smem exchange
//
// Fused neuron algebra (validated rounds 3/5): per stage
//   chain = E(a_0) C_0 G_0 T'(D1) C_1 G_1 ... T'(D9) C_9 G_9 F(a_9)
//   E(a)  = temporal [R(a), K+] ;  T'(D) = [K-, R(D), K+] ;  F(a) = [K-, R(-a)]
//   G_n   = rotation of anc0 on anc1=1 sectors, angle sign from outlane-n bit.
// F applied explicitly at stage end.

namespace {

constexpr int NTH   = 512;
constexpr int TT    = 9;
constexpr int NSTEP = 8;
constexpr int NIDX  = 22;   // 18 deltas + 2 entries + 2 trailings
constexpr int EP    = 9;    // exch stride (8 floats + 1 pad; 9 coprime 32)

__device__ __forceinline__ void ry_pair(float& a, float& b, float c, float s) {
    float a0 = a, b0 = b;
    a = fmaf(-s, b0, c * a0);
    b = fmaf( s, a0, c * b0);
}

template <int K>
__device__ __forceinline__ void ry_local(float* v, float c, float s) {
#pragma unroll
    for (int r = 0; r < 8; r++)
        if (!(r & (1 << K))) ry_pair(v[r], v[r | (1 << K)], c, s);
}

__device__ __forceinline__ void ry_shfl(float* v, int t, int m, float c, float s) {
    float se = (t & m) ? s : -s;
#pragma unroll
    for (int r = 0; r < 8; r++) {
        float w = __shfl_xor_sync(0xffffffffu, v[r], m);
        v[r] = fmaf(se, w, c * v[r]);
    }
}

// Combined RY(maskA-lane)*RY(maskB-lane): one smem round-trip, 4-way gather.
// (c0,s0) is the rotation on the ma bit; (c1,s1) on the mb bit.
__device__ __forceinline__ void ry_smem4(float* v, int t, int ma, int mb,
                                         float c0, float s0, float c1, float s1,
                                         float* exch) {
#pragma unroll
    for (int r = 0; r < 8; r++) exch[t * EP + r] = v[r];
    __syncthreads();
    int a  = (t & ma) ? 1 : 0;
    int bb = (t & mb) ? 1 : 0;
    float r0a0 = a  ? s0 : c0;
    float r0a1 = a  ? c0 : -s0;
    float r1b0 = bb ? s1 : c1;
    float r1b1 = bb ? c1 : -s1;
    float k00 = r0a0 * r1b0, k01 = r0a0 * r1b1;
    float k10 = r0a1 * r1b0, k11 = r0a1 * r1b1;
    int base = t & ~(ma | mb);
    const float* x00 = exch + base * EP;
    const float* x01 = exch + (base | mb) * EP;
    const float* x10 = exch + (base | ma) * EP;
    const float* x11 = exch + (base | ma | mb) * EP;
#pragma unroll
    for (int r = 0; r < 8; r++) {
        v[r] = fmaf(k00, x00[r],
               fmaf(k01, x01[r],
               fmaf(k10, x10[r], k11 * x11[r])));
    }
    __syncthreads();
}

// C = CiY(target = local r bit K, ctrl anc1 (r bit0 == 1))
template <int K>
__device__ __forceinline__ void ciy_local(float* v) {
#pragma unroll
    for (int r = 0; r < 8; r++)
        if ((r & 1) && !(r & (1 << K))) {
            float p0 = v[r];
            v[r] = v[r | (1 << K)];
            v[r | (1 << K)] = -p0;
        }
}

__device__ __forceinline__ void ciy_shfl(float* v, int t, int m) {
    float se = (t & m) ? -1.f : 1.f;
#pragma unroll
    for (int i = 0; i < 4; i++) {
        int r = 2 * i + 1;
        float w = __shfl_xor_sync(0xffffffffu, v[r], m);
        v[r] = se * w;
    }
}

__device__ __forceinline__ void ciy_smem(float* v, int t, int m, float* exch) {
#pragma unroll
    for (int i = 0; i < 4; i++) exch[t * EP + i] = v[2 * i + 1];
    __syncthreads();
    int p = t ^ m;
    float se = (t & m) ? -1.f : 1.f;
#pragma unroll
    for (int i = 0; i < 4; i++) v[2 * i + 1] = se * exch[p * EP + i];
    __syncthreads();
}

// v index r = (g<<2)|(anc0<<1)|anc1, g in 0..1: x0=(0,0) x1=(0,1) x2=(1,0) x3=(1,1)

// T'(D) = temporal [K-, R(D), K+]
__device__ __forceinline__ void applyT(float* v, float cb, float sb,
                                       const float* dc, const float* ds) {
#pragma unroll
    for (int g = 0; g < 2; g++) {
        float dcv = dc[g], dsv = ds[g];
        float c = fmaf(cb, dcv, -sb * dsv);
        float s = fmaf(sb, dcv,  cb * dsv);
        float x0 = v[4*g+0], x1 = v[4*g+1], x2 = v[4*g+2], x3 = v[4*g+3];
        v[4*g+0] = fmaf( s, x3, c * x0);
        v[4*g+1] = fmaf(-s, x2, c * x1);
        v[4*g+2] = fmaf( s, x1, c * x2);
        v[4*g+3] = fmaf(-s, x0, c * x3);
    }
}

// E(a) = temporal [R(a), K+]
__device__ __forceinline__ void applyE(float* v, float cb, float sb,
                                       const float* dc, const float* ds) {
#pragma unroll
    for (int g = 0; g < 2; g++) {
        float dcv = dc[g], dsv = ds[g];
        float c = fmaf(cb, dcv, -sb * dsv);
        float s = fmaf(sb, dcv,  cb * dsv);
        float x0 = v[4*g+0], x1 = v[4*g+1], x2 = v[4*g+2], x3 = v[4*g+3];
        v[4*g+0] = fmaf(-s, x2, c * x0);
        v[4*g+1] = fmaf(-s, x3, c * x1);
        v[4*g+2] = fmaf( s, x1, c * x3);
        v[4*g+3] = -fmaf( s, x0, c * x2);
    }
}

// F(a) = temporal [K-, R(-a)]
__device__ __forceinline__ void applyF(float* v, float cb, float sb,
                                       const float* dc, const float* ds) {
#pragma unroll
    for (int g = 0; g < 2; g++) {
        float dcv = dc[g], dsv = ds[g];
        float c = fmaf(cb, dcv, -sb * dsv);
        float s = fmaf(sb, dcv,  cb * dsv);
        float x0 = v[4*g+0], x1 = v[4*g+1], x2 = v[4*g+2], x3 = v[4*g+3];
        v[4*g+0] = fmaf(-s, x3, c * x0);
        v[4*g+1] = fmaf( s, x2, c * x1);
        v[4*g+2] = -fmaf( s, x0, c * x3);
        v[4*g+3] = fmaf(-s, x1, c * x2);
    }
}

// G: rotate (x1,x3) by signed angle; se carries sign (thread-uniform).
__device__ __forceinline__ void applyG(float* v, float c, float se) {
#pragma unroll
    for (int g = 0; g < 2; g++) {
        float x1 = v[4*g+1], x3 = v[4*g+3];
        v[4*g+1] = fmaf(-se, x3, c * x1);
        v[4*g+3] = fmaf( se, x1, c * x3);
    }
}
// sign from g bit0 (= lane9)
__device__ __forceinline__ void applyGg(float* v, float c, float s) {
#pragma unroll
    for (int g = 0; g < 2; g++) {
        float se = g ? s : -s;
        float x1 = v[4*g+1], x3 = v[4*g+3];
        v[4*g+1] = fmaf(-se, x3, c * x1);
        v[4*g+3] = fmaf( se, x1, c * x3);
    }
}

// angle-vector spec tables (compile-time):
//  0.. 8 : stage0 deltas  row(0,n)-row(0,n-1), n=1..9
//  9..17 : stage1 deltas  row(1,n)-row(1,n-1), n=1..9
//  18,19 : entries  row(0,0), row(1,0)
//  20,21 : trailing row(0,9), row(1,9)
__device__ constexpr int aIdx[NIDX] = {1,2,3,4,5,6,7,8,9, 11,12,13,14,15,16,17,18,19, 0, 10, 9, 19};
__device__ constexpr int bIdx[NIDX] = {0,1,2,3,4,5,6,7,8, 10,11,12,13,14,15,16,17,18, -1,-1,-1,-1};

__global__ void __launch_bounds__(NTH, 1) rvqe_kernel(
    const int*   __restrict__ inputs,   // (64, 9, 6) int32
    const float* __restrict__ ua,       // (2, 10)
    const float* __restrict__ nth,      // (2, 10, 11)
    float*       __restrict__ out,
    int out_size)
{
    __shared__ float exch[NTH * EP];
    __shared__ float uc[20], us[20];
    __shared__ float dcs[NIDX][2], dss[NIDX][2];   // delta table (lane9 only)
    __shared__ float gc_sm[20], gs_sm[20];
    __shared__ float probs_sm[64];
    __shared__ int   tIdx[TT];

    const int t = threadIdx.x;
    const int b = blockIdx.x;
    const int* inb = inputs + b * TT * 6;

    // ---- precompute ----
    if (t < 20) {
        float c, s; sincosf(0.5f * ua[t], &s, &c);
        uc[t] = c; us[t] = s;
        float cg, sg; sincosf(0.5f * nth[t * 11 + (t % 10)], &sg, &cg);
        gc_sm[t] = cg; gs_sm[t] = sg;
    }
    // delta part: g bit0 = lane9 (A[9])
    if (t < NIDX * 2) {
        int idx = t >> 1, g = t & 1;
        const float* A = nth + aIdx[idx] * 11;
        const float* Bp = (bIdx[idx] >= 0) ? (nth + bIdx[idx] * 11) : nullptr;
        float d = g ? (A[9] - (Bp ? Bp[9] : 0.f)) : 0.f;
        float c, s; sincosf(0.5f * d, &s, &c);
        dcs[idx][g] = c; dss[idx][g] = s;
    }
    if (t < TT) {
        int idx = 0;
#pragma unroll
        for (int i = 0; i < 6; i++) idx |= (inb[t * 6 + i] & 1) << (5 - i);
        tIdx[t] = idx;
    }

    // per-thread base trig in REGISTERS (lane i -> t bit (8-i), i=0..8)
    float cbs[NIDX], sbs[NIDX];
#pragma unroll
    for (int idx = 0; idx < NIDX; idx++) {
        const float* A = nth + aIdx[idx] * 11;
        const float* Bp = (bIdx[idx] >= 0) ? (nth + bIdx[idx] * 11) : nullptr;
        float base = A[10] - (Bp ? Bp[10] : 0.f);
#pragma unroll
        for (int i = 0; i < 9; i++)
            if ((t >> (8 - i)) & 1) base += A[i] - (Bp ? Bp[i] : 0.f);
        float c, s; sincosf(0.5f * base, &s, &c);
        cbs[idx] = c; sbs[idx] = s;
    }
    __syncthreads();

    // ---- init state: amplitude at g = tIdx[0]<<6 -> thread tIdx[0]<<3, r=0 ----
    float v[8];
#pragma unroll
    for (int r = 0; r < 8; r++) v[r] = 0.f;
    if (t == (tIdx[0] << 3)) v[0] = 1.f;

    for (int step = 0; step < NSTEP; step++) {
#pragma unroll
        for (int s = 0; s < 2; s++) {
            const float* ucc = uc + s * 10;
            const float* uss = us + s * 10;
            // stage RYs: lane9 local; lanes 4..8 shfl; lanes (0,1) and (2,3) 4-way smem
            ry_local<2>(v, ucc[9], uss[9]);
#pragma unroll
            for (int l = 4; l <= 8; l++)
                ry_shfl(v, t, 1 << (8 - l), ucc[l], uss[l]);
            ry_smem4(v, t, 256, 128, ucc[0], uss[0], ucc[1], uss[1], exch);
            ry_smem4(v, t,  64,  32, ucc[2], uss[2], ucc[3], uss[3], exch);

            // neuron chain: E C0 G0 T' C1 G1 ... T' C9 G9 F
            applyE(v, cbs[18 + s], sbs[18 + s], dcs[18 + s], dss[18 + s]);
            ciy_smem(v, t, 256, exch);                 // C0 (lane0 = t bit8)
            applyG(v, gc_sm[s * 10], ((t >> 8) & 1) ? gs_sm[s * 10] : -gs_sm[s * 10]);
#pragma unroll
            for (int n = 1; n < 10; n++) {
                int di = s * 9 + n - 1;
                applyT(v, cbs[di], sbs[di], dcs[di], dss[di]);
                if (n == 9) {
                    ciy_local<2>(v);                   // lane9 -> r bit2
                } else if (n >= 4) {
                    ciy_shfl(v, t, 1 << (8 - n));      // lanes 4..8
                } else {
                    ciy_smem(v, t, 1 << (8 - n), exch);// lanes 1,2,3
                }
                float cg = gc_sm[s * 10 + n], sg = gs_sm[s * 10 + n];
                if (n <= 8) applyG(v, cg, ((t >> (8 - n)) & 1) ? sg : -sg);
                else        applyGg(v, cg, sg);
            }
            applyF(v, cbs[20 + s], sbs[20 + s], dcs[20 + s], dss[20 + s]);
        }

        // ---- probs: out index j = t >> 3 (lanes 0..5); reduce over t bits 0..2 ----
        float ssq = 0.f;
#pragma unroll
        for (int r = 0; r < 8; r++) ssq = fmaf(v[r], v[r], ssq);
        ssq += __shfl_xor_sync(0xffffffffu, ssq, 1);
        ssq += __shfl_xor_sync(0xffffffffu, ssq, 2);
        ssq += __shfl_xor_sync(0xffffffffu, ssq, 4);
        if (!(t & 7)) {
            probs_sm[t >> 3] = ssq;
            out[(b * NSTEP + step) * 64 + (t >> 3)] = ssq;
        }
        __syncthreads();

        // ---- project + normalize; cond_flips cancel across steps ----
        int tj = tIdx[step + 1];
        float invn = 1.0f / sqrtf(probs_sm[tj]);
        if ((t >> 3) == tj) {
#pragma unroll
            for (int r = 0; r < 8; r++) v[r] *= invn;
        } else {
#pragma unroll
            for (int r = 0; r < 8; r++) v[r] = 0.f;
        }
    }

    // ---- second tuple output: measured = inputs[:,1:] as float ----
    if (out_size > 32768 && t < 48) {
        out[32768 + b * 48 + t] = (float)inb[6 + t];
    }
}

} // namespace

extern "C" void kernel_launch(void* const* d_in, const int* in_sizes, int n_in,
                              void* d_out, int out_size) {
    const int*   inputs = nullptr;
    const float* ua     = nullptr;
    const float* nth    = nullptr;
    for (int i = 0; i < n_in; i++) {
        if (in_sizes[i] == 3456)      inputs = (const int*)d_in[i];
        else if (in_sizes[i] == 20)   ua     = (const float*)d_in[i];
        else if (in_sizes[i] == 220)  nth    = (const float*)d_in[i];
    }
    rvqe_kernel<<<64, NTH>>>(inputs, ua, nth, (float*)d_out, out_size);
}

// round 7
// speedup vs baseline: 1.0400x; 1.0400x over previous
#include <cuda_runtime.h>
#include <math.h>
#include <stdint.h>

// RVQE: 12-qubit real statevector recurrent cell, B=64, T=9 (8 scan steps).
// One CTA per batch element; state = 4096 floats = 256 threads x 16 registers.
// Global amplitude index g (12 bits), g = (t << 4) | r:
//   r bits: bit0=lane11(anc1), bit1=lane10(anc0), bit2=lane9, bit3=lane8
//   t bits 0..4 (warp lane): lanes 7,6,5,4,3  -> __shfl_xor (mask 1<<(7-lane))
//   t bits 5,6,7 (warp id bits 0,1,2): lanes 2,1,0 -> smem exchange
//
// Fused neuron algebra (validated rounds 3/5): per stage
//   chain = E(a_0) C_0 G_0 T'(D1) C_1 G_1 ... T'(D9) C_9 G_9 F(a_9)
// Barrier scheme (this round):
//   - all 3 smem stage-RYs fused into ONE 8-way gather (1 full __syncthreads)
//   - each smem CiY uses a DEDICATED buffer + ONE named 2-warp barrier
//     (ids 1-4 for mask128, 5-8 for mask64, 9-12 for mask32). Buffer-reuse
//     across stages is ordered by the full sync inside ry_smem8; R-buffer
//     reuse is ordered transitively through the pair barriers (each of bits
//     5/6/7 has a covering pair barrier between consecutive ry_smem8 uses).

namespace {

constexpr int NTH   = 256;
constexpr int TT    = 9;
constexpr int NSTEP = 8;
constexpr int NIDX  = 22;   // 18 deltas + 2 entries + 2 trailings
constexpr int RP    = 17;   // ry buffer stride (16 + 1 pad)
constexpr int CP    = 9;    // ciy buffer stride (8 + 1 pad)

#define NBAR64(id) asm volatile("bar.sync %0, 64;" :: "r"(id) : "memory")

__device__ __forceinline__ void ry_pair(float& a, float& b, float c, float s) {
    float a0 = a, b0 = b;
    a = fmaf(-s, b0, c * a0);
    b = fmaf( s, a0, c * b0);
}

template <int K>
__device__ __forceinline__ void ry_local(float* v, float c, float s) {
#pragma unroll
    for (int r = 0; r < 16; r++)
        if (!(r & (1 << K))) ry_pair(v[r], v[r | (1 << K)], c, s);
}

__device__ __forceinline__ void ry_shfl(float* v, int t, int m, float c, float s) {
    float se = (t & m) ? s : -s;
#pragma unroll
    for (int r = 0; r < 16; r++) {
        float w = __shfl_xor_sync(0xffffffffu, v[r], m);
        v[r] = fmaf(se, w, c * v[r]);
    }
}

// Fused RY(lane0)*RY(lane1)*RY(lane2) on t bits 7,6,5: one full-sync 8-way gather.
__device__ __forceinline__ void ry_smem8(float* v, int t,
                                         float c0, float s0, float c1, float s1,
                                         float c2, float s2, float* R) {
#pragma unroll
    for (int r = 0; r < 16; r++) R[t * RP + r] = v[r];
    __syncthreads();
    float F0 = (t & 128) ? s0 : -s0;
    float F1 = (t &  64) ? s1 : -s1;
    float F2 = (t &  32) ? s2 : -s2;
    float k[8];
    const float* rows[8];
#pragma unroll
    for (int d = 0; d < 8; d++) {
        float kk = (d & 4) ? F0 : c0;
        kk *= (d & 2) ? F1 : c1;
        kk *= (d & 1) ? F2 : c2;
        k[d] = kk;
        int m = ((d & 4) ? 128 : 0) | ((d & 2) ? 64 : 0) | ((d & 1) ? 32 : 0);
        rows[d] = R + (t ^ m) * RP;
    }
#pragma unroll
    for (int r = 0; r < 16; r++) {
        float acc = k[0] * rows[0][r];
#pragma unroll
        for (int d = 1; d < 8; d++) acc = fmaf(k[d], rows[d][r], acc);
        v[r] = acc;
    }
}

// C = CiY(target = local r bit K, ctrl anc1 (r bit0 == 1))
template <int K>
__device__ __forceinline__ void ciy_local(float* v) {
#pragma unroll
    for (int r = 0; r < 16; r++)
        if ((r & 1) && !(r & (1 << K))) {
            float p0 = v[r];
            v[r] = v[r | (1 << K)];
            v[r | (1 << K)] = -p0;
        }
}

__device__ __forceinline__ void ciy_shfl(float* v, int t, int m) {
    float se = (t & m) ? -1.f : 1.f;
#pragma unroll
    for (int i = 0; i < 8; i++) {
        int r = 2 * i + 1;
        float w = __shfl_xor_sync(0xffffffffu, v[r], m);
        v[r] = se * w;
    }
}

// CiY across warps: dedicated buffer, ONE named 2-warp barrier.
__device__ __forceinline__ void ciy_nb(float* v, int t, int m, float* buf, int id) {
#pragma unroll
    for (int i = 0; i < 8; i++) buf[t * CP + i] = v[2 * i + 1];
    NBAR64(id);
    const float* p = buf + (t ^ m) * CP;
    float se = (t & m) ? -1.f : 1.f;
#pragma unroll
    for (int i = 0; i < 8; i++) v[2 * i + 1] = se * p[i];
}

// v index r = (g<<2)|(anc0<<1)|anc1, g in 0..3: x0=(0,0) x1=(0,1) x2=(1,0) x3=(1,1)

// T'(D) = temporal [K-, R(D), K+]
__device__ __forceinline__ void applyT(float* v, float cb, float sb,
                                       const float* dc, const float* ds) {
#pragma unroll
    for (int g = 0; g < 4; g++) {
        float dcv = dc[g], dsv = ds[g];
        float c = fmaf(cb, dcv, -sb * dsv);
        float s = fmaf(sb, dcv,  cb * dsv);
        float x0 = v[4*g+0], x1 = v[4*g+1], x2 = v[4*g+2], x3 = v[4*g+3];
        v[4*g+0] = fmaf( s, x3, c * x0);
        v[4*g+1] = fmaf(-s, x2, c * x1);
        v[4*g+2] = fmaf( s, x1, c * x2);
        v[4*g+3] = fmaf(-s, x0, c * x3);
    }
}

// E(a) = temporal [R(a), K+]
__device__ __forceinline__ void applyE(float* v, float cb, float sb,
                                       const float* dc, const float* ds) {
#pragma unroll
    for (int g = 0; g < 4; g++) {
        float dcv = dc[g], dsv = ds[g];
        float c = fmaf(cb, dcv, -sb * dsv);
        float s = fmaf(sb, dcv,  cb * dsv);
        float x0 = v[4*g+0], x1 = v[4*g+1], x2 = v[4*g+2], x3 = v[4*g+3];
        v[4*g+0] = fmaf(-s, x2, c * x0);
        v[4*g+1] = fmaf(-s, x3, c * x1);
        v[4*g+2] = fmaf( s, x1, c * x3);
        v[4*g+3] = -fmaf( s, x0, c * x2);
    }
}

// F(a) = temporal [K-, R(-a)]
__device__ __forceinline__ void applyF(float* v, float cb, float sb,
                                       const float* dc, const float* ds) {
#pragma unroll
    for (int g = 0; g < 4; g++) {
        float dcv = dc[g], dsv = ds[g];
        float c = fmaf(cb, dcv, -sb * dsv);
        float s = fmaf(sb, dcv,  cb * dsv);
        float x0 = v[4*g+0], x1 = v[4*g+1], x2 = v[4*g+2], x3 = v[4*g+3];
        v[4*g+0] = fmaf(-s, x3, c * x0);
        v[4*g+1] = fmaf( s, x2, c * x1);
        v[4*g+2] = -fmaf( s, x0, c * x3);
        v[4*g+3] = fmaf(-s, x1, c * x2);
    }
}

// G: rotate (x1,x3) by signed angle; se carries sign (thread-uniform).
__device__ __forceinline__ void applyG(float* v, float c, float se) {
#pragma unroll
    for (int g = 0; g < 4; g++) {
        float x1 = v[4*g+1], x3 = v[4*g+3];
        v[4*g+1] = fmaf(-se, x3, c * x1);
        v[4*g+3] = fmaf( se, x1, c * x3);
    }
}
template <int GB>  // sign from g bit GB (GB=0 -> lane9, GB=1 -> lane8)
__device__ __forceinline__ void applyGg(float* v, float c, float s) {
#pragma unroll
    for (int g = 0; g < 4; g++) {
        float se = (g & (1 << GB)) ? s : -s;
        float x1 = v[4*g+1], x3 = v[4*g+3];
        v[4*g+1] = fmaf(-se, x3, c * x1);
        v[4*g+3] = fmaf( se, x1, c * x3);
    }
}

// angle-vector spec tables:
//  0.. 8 : stage0 deltas  row(0,n)-row(0,n-1), n=1..9
//  9..17 : stage1 deltas  row(1,n)-row(1,n-1), n=1..9
//  18,19 : entries  row(0,0), row(1,0)
//  20,21 : trailing row(0,9), row(1,9)
__device__ constexpr int aIdx[NIDX] = {1,2,3,4,5,6,7,8,9, 11,12,13,14,15,16,17,18,19, 0, 10, 9, 19};
__device__ constexpr int bIdx[NIDX] = {0,1,2,3,4,5,6,7,8, 10,11,12,13,14,15,16,17,18, -1,-1,-1,-1};

__global__ void __launch_bounds__(NTH, 1) rvqe_kernel(
    const int*   __restrict__ inputs,   // (64, 9, 6) int32
    const float* __restrict__ ua,       // (2, 10)
    const float* __restrict__ nth,      // (2, 10, 11)
    float*       __restrict__ out,
    int out_size)
{
    __shared__ float exchR[NTH * RP];      // ry_smem8 buffer
    __shared__ float p128[NTH * CP];       // ciy mask 128 buffer
    __shared__ float p64 [NTH * CP];       // ciy mask 64 buffer
    __shared__ float p32 [NTH * CP];       // ciy mask 32 buffer
    __shared__ float uc[20], us[20];
    __shared__ float dcs[NIDX][4], dss[NIDX][4];   // delta tables (lanes 8,9)
    __shared__ float gc_sm[20], gs_sm[20];
    __shared__ float probs_sm[64];
    __shared__ int   tIdx[TT];

    const int t = threadIdx.x;
    const int b = blockIdx.x;
    const int w = t >> 5;
    const int* inb = inputs + b * TT * 6;

    // named barrier ids (group-invariant per mask)
    const int id128 = 1 + (w & 3);                       // partner w^4
    const int id64  = 5 + ((w & 1) | ((w >> 1) & 2));    // partner w^2
    const int id32  = 9 + ((w >> 1) & 3);                // partner w^1

    // ---- precompute ----
    if (t < 20) {
        float c, s; sincosf(0.5f * ua[t], &s, &c);
        uc[t] = c; us[t] = s;
        float cg, sg; sincosf(0.5f * nth[t * 11 + (t % 10)], &sg, &cg);
        gc_sm[t] = cg; gs_sm[t] = sg;
    }
    // delta part: g bit0 = lane9 (A[9]), g bit1 = lane8 (A[8])
    if (t < NIDX * 4) {
        int idx = t >> 2, g = t & 3;
        const float* A = nth + aIdx[idx] * 11;
        const float* Bp = (bIdx[idx] >= 0) ? (nth + bIdx[idx] * 11) : nullptr;
        float d = 0.f;
        if (g & 1) d += A[9] - (Bp ? Bp[9] : 0.f);
        if (g & 2) d += A[8] - (Bp ? Bp[8] : 0.f);
        float c, s; sincosf(0.5f * d, &s, &c);
        dcs[idx][g] = c; dss[idx][g] = s;
    }
    if (t < TT) {
        int idx = 0;
#pragma unroll
        for (int i = 0; i < 6; i++) idx |= (inb[t * 6 + i] & 1) << (5 - i);
        tIdx[t] = idx;
    }

    // per-thread base trig in REGISTERS (lane i -> t bit (7-i), i=0..7)
    float cbs[NIDX], sbs[NIDX];
#pragma unroll
    for (int idx = 0; idx < NIDX; idx++) {
        const float* A = nth + aIdx[idx] * 11;
        const float* Bp = (bIdx[idx] >= 0) ? (nth + bIdx[idx] * 11) : nullptr;
        float base = A[10] - (Bp ? Bp[10] : 0.f);
#pragma unroll
        for (int i = 0; i < 8; i++)
            if ((t >> (7 - i)) & 1) base += A[i] - (Bp ? Bp[i] : 0.f);
        float c, s; sincosf(0.5f * base, &s, &c);
        cbs[idx] = c; sbs[idx] = s;
    }
    __syncthreads();

    // ---- init state: amplitude at g = tIdx[0]<<6 -> thread tIdx[0]<<2, r=0 ----
    float v[16];
#pragma unroll
    for (int r = 0; r < 16; r++) v[r] = 0.f;
    if (t == (tIdx[0] << 2)) v[0] = 1.f;

    for (int step = 0; step < NSTEP; step++) {
#pragma unroll
        for (int s = 0; s < 2; s++) {
            const float* ucc = uc + s * 10;
            const float* uss = us + s * 10;
            // stage RYs: lanes 8,9 local; lanes 3..7 shfl; lanes 0,1,2 fused smem
            ry_local<3>(v, ucc[8], uss[8]);
            ry_local<2>(v, ucc[9], uss[9]);
#pragma unroll
            for (int l = 3; l <= 7; l++)
                ry_shfl(v, t, 1 << (7 - l), ucc[l], uss[l]);
            ry_smem8(v, t, ucc[0], uss[0], ucc[1], uss[1], ucc[2], uss[2], exchR);

            // neuron chain: E C0 G0 T' C1 G1 ... T' C9 G9 F
            applyE(v, cbs[18 + s], sbs[18 + s], dcs[18 + s], dss[18 + s]);
            ciy_nb(v, t, 128, p128, id128);            // C0 (lane0 = t bit7)
            applyG(v, gc_sm[s * 10], ((t >> 7) & 1) ? gs_sm[s * 10] : -gs_sm[s * 10]);
#pragma unroll
            for (int n = 1; n < 10; n++) {
                int di = s * 9 + n - 1;
                applyT(v, cbs[di], sbs[di], dcs[di], dss[di]);
                if (n >= 8) {
                    if (n == 8) ciy_local<3>(v);       // lane8 -> r bit3
                    else        ciy_local<2>(v);       // lane9 -> r bit2
                } else if (n >= 3) {
                    ciy_shfl(v, t, 1 << (7 - n));      // lanes 3..7
                } else if (n == 1) {
                    ciy_nb(v, t, 64, p64, id64);       // lane1 = t bit6
                } else {
                    ciy_nb(v, t, 32, p32, id32);       // lane2 = t bit5
                }
                float cg = gc_sm[s * 10 + n], sg = gs_sm[s * 10 + n];
                if (n <= 7)      applyG(v, cg, ((t >> (7 - n)) & 1) ? sg : -sg);
                else if (n == 8) applyGg<1>(v, cg, sg);
                else             applyGg<0>(v, cg, sg);
            }
            applyF(v, cbs[20 + s], sbs[20 + s], dcs[20 + s], dss[20 + s]);
        }

        // ---- probs: out index j = t >> 2 (lanes 0..5); reduce over t bits 0,1 ----
        float ssq = 0.f;
#pragma unroll
        for (int r = 0; r < 16; r++) ssq = fmaf(v[r], v[r], ssq);
        ssq += __shfl_xor_sync(0xffffffffu, ssq, 1);
        ssq += __shfl_xor_sync(0xffffffffu, ssq, 2);
        if (!(t & 3)) {
            probs_sm[t >> 2] = ssq;
            out[(b * NSTEP + step) * 64 + (t >> 2)] = ssq;
        }
        __syncthreads();

        // ---- project + normalize; cond_flips cancel across steps ----
        int tj = tIdx[step + 1];
        float invn = 1.0f / sqrtf(probs_sm[tj]);
        if ((t >> 2) == tj) {
#pragma unroll
            for (int r = 0; r < 16; r++) v[r] *= invn;
        } else {
#pragma unroll
            for (int r = 0; r < 16; r++) v[r] = 0.f;
        }
    }

    // ---- second tuple output: measured = inputs[:,1:] as float ----
    if (out_size > 32768 && t < 48) {
        out[32768 + b * 48 + t] = (float)inb[6 + t];
    }
}

} // namespace

extern "C" void kernel_launch(void* const* d_in, const int* in_sizes, int n_in,
                              void* d_out, int out_size) {
    const int*   inputs = nullptr;
    const float* ua     = nullptr;
    const float* nth    = nullptr;
    for (int i = 0; i < n_in; i++) {
        if (in_sizes[i] == 3456)      inputs = (const int*)d_in[i];
        else if (in_sizes[i] == 20)   ua     = (const float*)d_in[i];
        else if (in_sizes[i] == 220)  nth    = (const float*)d_in[i];
    }
    rvqe_kernel<<<64, NTH>>>(inputs, ua, nth, (float*)d_out, out_size);
}

// round 8
// speedup vs baseline: 1.1803x; 1.1348x over previous
#include <cuda_runtime.h>
#include <math.h>
#include <stdint.h>

// RVQE: 12-qubit real statevector recurrent cell, B=64, T=9 (8 scan steps).
// One CTA per batch element; state = 4096 floats = 256 threads x 8 packed f32x2.
// Global amplitude index g12 (12 bits), g12 = (t << 4) | r:
//   r bits: bit0=lane11(anc1), bit1=lane10(anc0), bit2=lane9, bit3=lane8
//   t bits 0..4 (warp lane): lanes 7,6,5,4,3  -> __shfl_xor (mask 1<<(7-lane))
//   t bits 5,6,7: lanes 2,1,0 -> smem exchange
// PACKING: P[j], j = a*4 + i, i = (anc0<<1)|anc1, a = lane8 bit.
//   P[j].lo = state at lane9=0 (g even), P[j].hi = lane9=1 (g odd).
// All rotations use packed f32x2 FMA (Blackwell); lane9-axis ops use an
// intra-pair swap or packed (-s,+s) constants. CiY signs are integer XORs.
//
// Fused neuron algebra (validated rounds 3/5): per stage
//   chain = E(a_0) C_0 G_0 T'(D1) C_1 G_1 ... T'(D9) C_9 G_9 F(a_9)

namespace {

typedef unsigned long long u64;

constexpr int NTH   = 256;
constexpr int TT    = 9;
constexpr int NSTEP = 8;
constexpr int NIDX  = 22;   // 18 deltas + 2 entries + 2 trailings
constexpr int STq   = 9;    // exch stride in u64 (8 + 1 pad; odd -> conflict-free)
constexpr u64 SGN2  = 0x8000000080000000ULL;

__device__ __forceinline__ u64 pk(float lo, float hi) {
    u64 r; asm("mov.b64 %0,{%1,%2};" : "=l"(r) : "f"(lo), "f"(hi)); return r;
}
__device__ __forceinline__ void upk(u64 u, float& lo, float& hi) {
    asm("mov.b64 {%0,%1},%2;" : "=f"(lo), "=f"(hi) : "l"(u));
}
__device__ __forceinline__ u64 bc(float x) { return pk(x, x); }
__device__ __forceinline__ u64 f2mul(u64 a, u64 b) {
    u64 d; asm("mul.rn.f32x2 %0,%1,%2;" : "=l"(d) : "l"(a), "l"(b)); return d;
}
__device__ __forceinline__ u64 f2fma(u64 a, u64 b, u64 c) {
    u64 d; asm("fma.rn.f32x2 %0,%1,%2,%3;" : "=l"(d) : "l"(a), "l"(b), "l"(c)); return d;
}
__device__ __forceinline__ u64 f2neg(u64 a) { return a ^ SGN2; }
__device__ __forceinline__ u64 f2swap(u64 a) { float lo, hi; upk(a, lo, hi); return pk(hi, lo); }

// ---- stage RY pieces ----

// RY on lane9 (the packed dim): u' = C*u + (-s,+s)*swap(u)
__device__ __forceinline__ void ry_lane9(u64* P, u64 C, u64 SW) {
#pragma unroll
    for (int j = 0; j < 8; j++)
        P[j] = f2fma(SW, f2swap(P[j]), f2mul(C, P[j]));
}

// RY on lane8 (a bit): cross-reg, element-wise packed
__device__ __forceinline__ void ry_lane8(u64* P, float c, float s) {
    u64 C = bc(c), S = bc(s), NS = bc(-s);
#pragma unroll
    for (int i = 0; i < 4; i++) {
        u64 u = P[i], w = P[4 + i];
        P[i]     = f2fma(NS, w, f2mul(C, u));
        P[4 + i] = f2fma(S,  u, f2mul(C, w));
    }
}

__device__ __forceinline__ void ry_shfl(u64* P, int t, int m, float c, float s) {
    u64 C = bc(c), SE = bc((t & m) ? s : -s);
#pragma unroll
    for (int j = 0; j < 8; j++) {
        u64 w = __shfl_xor_sync(0xffffffffu, P[j], m);
        P[j] = f2fma(SE, w, f2mul(C, P[j]));
    }
}

// Combined RY(lane0)*RY(lane1) (t bits 7,6): one round-trip, 4-way gather.
__device__ __forceinline__ void ry_smem4(u64* P, int t,
                                         float c0, float s0, float c1, float s1,
                                         u64* X) {
#pragma unroll
    for (int j = 0; j < 8; j++) X[t * STq + j] = P[j];
    __syncthreads();
    int a  = (t >> 7) & 1;
    int bb = (t >> 6) & 1;
    float r0a0 = a  ? s0 : c0;
    float r0a1 = a  ? c0 : -s0;
    float r1b0 = bb ? s1 : c1;
    float r1b1 = bb ? c1 : -s1;
    u64 k00 = bc(r0a0 * r1b0), k01 = bc(r0a0 * r1b1);
    u64 k10 = bc(r0a1 * r1b0), k11 = bc(r0a1 * r1b1);
    int base = t & 63;
    const u64* x00 = X + base * STq;
    const u64* x01 = X + (base | 64)  * STq;
    const u64* x10 = X + (base | 128) * STq;
    const u64* x11 = X + (base | 192) * STq;
#pragma unroll
    for (int j = 0; j < 8; j++)
        P[j] = f2fma(k00, x00[j],
               f2fma(k01, x01[j],
               f2fma(k10, x10[j], f2mul(k11, x11[j]))));
    __syncthreads();
}

// RY on lane2 (t bit5): 2-way exchange.
__device__ __forceinline__ void ry_smem1(u64* P, int t, float c, float s, u64* X) {
#pragma unroll
    for (int j = 0; j < 8; j++) X[t * STq + j] = P[j];
    __syncthreads();
    const u64* xp = X + (t ^ 32) * STq;
    u64 C = bc(c), SE = bc((t & 32) ? s : -s);
#pragma unroll
    for (int j = 0; j < 8; j++) P[j] = f2fma(SE, xp[j], f2mul(C, P[j]));
    __syncthreads();
}

// ---- CiY pieces (ctrl anc1: i odd -> j in {1,3,5,7}) ----

// target lane9 (packed dim): u' = (hi, -lo)
__device__ __forceinline__ void ciy_lane9(u64* P) {
#pragma unroll
    for (int j = 1; j < 8; j += 2) {
        float lo, hi; upk(P[j], lo, hi);
        P[j] = pk(hi, -lo);
    }
}

// target lane8 (a bit): swap a=0 <-> a=1 with negation
__device__ __forceinline__ void ciy_lane8(u64* P) {
#pragma unroll
    for (int i = 1; i < 4; i += 2) {
        u64 p0 = P[i];
        P[i] = P[4 + i];
        P[4 + i] = f2neg(p0);
    }
}

__device__ __forceinline__ void ciy_shfl(u64* P, int t, int m) {
    u64 sgn = (t & m) ? SGN2 : 0ULL;
#pragma unroll
    for (int j = 1; j < 8; j += 2) {
        u64 w = __shfl_xor_sync(0xffffffffu, P[j], m);
        P[j] = w ^ sgn;
    }
}

__device__ __forceinline__ void ciy_smem(u64* P, int t, int m, u64* X) {
#pragma unroll
    for (int j = 1; j < 8; j += 2) X[t * STq + (j >> 1)] = P[j];
    __syncthreads();
    const u64* p = X + (t ^ m) * STq;
    u64 sgn = (t & m) ? SGN2 : 0ULL;
#pragma unroll
    for (int j = 1; j < 8; j += 2) P[j] = p[j >> 1] ^ sgn;
    __syncthreads();
}

// ---- fused neuron ops (packed over lane9; loop over a) ----
// x_i = P[a*4+i]: x0=(0,0) x1=(0,1) x2=(1,0) x3=(1,1) of (anc0,anc1)

// T'(D) = temporal [K-, R(D), K+]
__device__ __forceinline__ void applyT(u64* P, float cb, float sb,
                                       const u64* DC, const u64* DS) {
    u64 CB = bc(cb), SB = bc(sb), NSB = bc(-sb);
#pragma unroll
    for (int a = 0; a < 2; a++) {
        u64 C  = f2fma(NSB, DS[a], f2mul(CB, DC[a]));
        u64 S  = f2fma(SB,  DC[a], f2mul(CB, DS[a]));
        u64 NS = f2neg(S);
        u64 x0 = P[4*a+0], x1 = P[4*a+1], x2 = P[4*a+2], x3 = P[4*a+3];
        P[4*a+0] = f2fma(S,  x3, f2mul(C, x0));
        P[4*a+1] = f2fma(NS, x2, f2mul(C, x1));
        P[4*a+2] = f2fma(S,  x1, f2mul(C, x2));
        P[4*a+3] = f2fma(NS, x0, f2mul(C, x3));
    }
}

// E(a) = temporal [R(a), K+]
__device__ __forceinline__ void applyE(u64* P, float cb, float sb,
                                       const u64* DC, const u64* DS) {
    u64 CB = bc(cb), SB = bc(sb), NSB = bc(-sb);
#pragma unroll
    for (int a = 0; a < 2; a++) {
        u64 C  = f2fma(NSB, DS[a], f2mul(CB, DC[a]));
        u64 S  = f2fma(SB,  DC[a], f2mul(CB, DS[a]));
        u64 NS = f2neg(S);
        u64 x0 = P[4*a+0], x1 = P[4*a+1], x2 = P[4*a+2], x3 = P[4*a+3];
        P[4*a+0] = f2fma(NS, x2, f2mul(C, x0));
        P[4*a+1] = f2fma(NS, x3, f2mul(C, x1));
        P[4*a+2] = f2fma(S,  x1, f2mul(C, x3));
        P[4*a+3] = f2neg(f2fma(S, x0, f2mul(C, x2)));
    }
}

// F(a) = temporal [K-, R(-a)]
__device__ __forceinline__ void applyF(u64* P, float cb, float sb,
                                       const u64* DC, const u64* DS) {
    u64 CB = bc(cb), SB = bc(sb), NSB = bc(-sb);
#pragma unroll
    for (int a = 0; a < 2; a++) {
        u64 C  = f2fma(NSB, DS[a], f2mul(CB, DC[a]));
        u64 S  = f2fma(SB,  DC[a], f2mul(CB, DS[a]));
        u64 NS = f2neg(S);
        u64 x0 = P[4*a+0], x1 = P[4*a+1], x2 = P[4*a+2], x3 = P[4*a+3];
        P[4*a+0] = f2fma(NS, x3, f2mul(C, x0));
        P[4*a+1] = f2fma(S,  x2, f2mul(C, x1));
        P[4*a+2] = f2neg(f2fma(S, x0, f2mul(C, x3)));
        P[4*a+3] = f2fma(NS, x1, f2mul(C, x2));
    }
}

// G with packed sign SE (covers thread-sign, a-sign, lane9-sign cases)
__device__ __forceinline__ void applyG_se(u64* P, u64 C, u64 SE0, u64 SE1) {
    u64 NSE0 = f2neg(SE0), NSE1 = f2neg(SE1);
    {
        u64 x1 = P[1], x3 = P[3];
        P[1] = f2fma(NSE0, x3, f2mul(C, x1));
        P[3] = f2fma(SE0,  x1, f2mul(C, x3));
    }
    {
        u64 x1 = P[5], x3 = P[7];
        P[5] = f2fma(NSE1, x3, f2mul(C, x1));
        P[7] = f2fma(SE1,  x1, f2mul(C, x3));
    }
}

// angle-vector spec tables:
//  0.. 8 : stage0 deltas  row(0,n)-row(0,n-1), n=1..9
//  9..17 : stage1 deltas  row(1,n)-row(1,n-1), n=1..9
//  18,19 : entries  row(0,0), row(1,0)
//  20,21 : trailing row(0,9), row(1,9)
__device__ constexpr int aIdx[NIDX] = {1,2,3,4,5,6,7,8,9, 11,12,13,14,15,16,17,18,19, 0, 10, 9, 19};
__device__ constexpr int bIdx[NIDX] = {0,1,2,3,4,5,6,7,8, 10,11,12,13,14,15,16,17,18, -1,-1,-1,-1};

__global__ void __launch_bounds__(NTH, 1) rvqe_kernel(
    const int*   __restrict__ inputs,   // (64, 9, 6) int32
    const float* __restrict__ ua,       // (2, 10)
    const float* __restrict__ nth,      // (2, 10, 11)
    float*       __restrict__ out,
    int out_size)
{
    __shared__ u64   exch[NTH * STq];
    __shared__ float uc[20], us[20];
    __shared__ u64   DC2[NIDX][2], DS2[NIDX][2];   // packed delta trig: (lane9=0, lane9=1)
    __shared__ float gc_sm[20], gs_sm[20];
    __shared__ u64   se9p[2];                      // packed (-s,+s) for n=9 G, per stage
    __shared__ float probs_sm[64];
    __shared__ int   tIdx[TT];

    const int t = threadIdx.x;
    const int b = blockIdx.x;
    const int* inb = inputs + b * TT * 6;

    // ---- precompute ----
    if (t < 20) {
        float c, s; sincosf(0.5f * ua[t], &s, &c);
        uc[t] = c; us[t] = s;
        float cg, sg; sincosf(0.5f * nth[t * 11 + (t % 10)], &sg, &cg);
        gc_sm[t] = cg; gs_sm[t] = sg;
        if ((t % 10) == 9) se9p[t / 10] = pk(-sg, sg);
    }
    // packed delta trig: a = lane8 bit; lo half lane9=0, hi half lane9=1
    if (t < NIDX * 2) {
        int idx = t >> 1, a = t & 1;
        const float* A = nth + aIdx[idx] * 11;
        const float* Bp = (bIdx[idx] >= 0) ? (nth + bIdx[idx] * 11) : nullptr;
        float d8 = A[8] - (Bp ? Bp[8] : 0.f);
        float d9 = A[9] - (Bp ? Bp[9] : 0.f);
        float dlo = a ? d8 : 0.f;
        float dhi = dlo + d9;
        float cl, sl, ch, sh;
        sincosf(0.5f * dlo, &sl, &cl);
        sincosf(0.5f * dhi, &sh, &ch);
        DC2[idx][a] = pk(cl, ch);
        DS2[idx][a] = pk(sl, sh);
    }
    if (t < TT) {
        int idx = 0;
#pragma unroll
        for (int i = 0; i < 6; i++) idx |= (inb[t * 6 + i] & 1) << (5 - i);
        tIdx[t] = idx;
    }

    // per-thread base trig in REGISTERS (lane i -> t bit (7-i), i=0..7)
    float cbs[NIDX], sbs[NIDX];
#pragma unroll
    for (int idx = 0; idx < NIDX; idx++) {
        const float* A = nth + aIdx[idx] * 11;
        const float* Bp = (bIdx[idx] >= 0) ? (nth + bIdx[idx] * 11) : nullptr;
        float base = A[10] - (Bp ? Bp[10] : 0.f);
#pragma unroll
        for (int i = 0; i < 8; i++)
            if ((t >> (7 - i)) & 1) base += A[i] - (Bp ? Bp[i] : 0.f);
        float c, s; sincosf(0.5f * base, &s, &c);
        cbs[idx] = c; sbs[idx] = s;
    }
    __syncthreads();

    // ---- init state: amplitude at g12 = tIdx[0]<<6 -> thread tIdx[0]<<2, r=0 (lo of P[0]) ----
    u64 P[8];
#pragma unroll
    for (int j = 0; j < 8; j++) P[j] = 0ULL;
    if (t == (tIdx[0] << 2)) P[0] = pk(1.f, 0.f);

    for (int step = 0; step < NSTEP; step++) {
#pragma unroll
        for (int s = 0; s < 2; s++) {
            const float* ucc = uc + s * 10;
            const float* uss = us + s * 10;
            // stage RYs: lane8 cross-reg, lane9 intra-pair; lanes 3..7 shfl; 0,1,2 smem
            ry_lane8(P, ucc[8], uss[8]);
            {
                u64 C9 = bc(ucc[9]);
                u64 SW = pk(-uss[9], uss[9]);
                ry_lane9(P, C9, SW);
            }
#pragma unroll
            for (int l = 3; l <= 7; l++)
                ry_shfl(P, t, 1 << (7 - l), ucc[l], uss[l]);
            ry_smem4(P, t, ucc[0], uss[0], ucc[1], uss[1], exch);
            ry_smem1(P, t, ucc[2], uss[2], exch);

            // neuron chain: E C0 G0 T' C1 G1 ... T' C9 G9 F
            applyE(P, cbs[18 + s], sbs[18 + s], DC2[18 + s], DS2[18 + s]);
            ciy_smem(P, t, 128, exch);                 // C0 (lane0 = t bit7)
            {
                float sg = ((t >> 7) & 1) ? gs_sm[s * 10] : -gs_sm[s * 10];
                u64 SE = bc(sg);
                applyG_se(P, bc(gc_sm[s * 10]), SE, SE);
            }
#pragma unroll
            for (int n = 1; n < 10; n++) {
                int di = s * 9 + n - 1;
                applyT(P, cbs[di], sbs[di], DC2[di], DS2[di]);
                if (n == 9) {
                    ciy_lane9(P);
                } else if (n == 8) {
                    ciy_lane8(P);
                } else if (n >= 3) {
                    ciy_shfl(P, t, 1 << (7 - n));
                } else {
                    ciy_smem(P, t, (n == 1) ? 64 : 32, exch);
                }
                int gi = s * 10 + n;
                u64 C = bc(gc_sm[gi]);
                if (n <= 7) {
                    float sg = ((t >> (7 - n)) & 1) ? gs_sm[gi] : -gs_sm[gi];
                    u64 SE = bc(sg);
                    applyG_se(P, C, SE, SE);
                } else if (n == 8) {
                    u64 SE1 = bc(gs_sm[gi]);       // a=1 -> +s, a=0 -> -s
                    applyG_se(P, C, f2neg(SE1), SE1);
                } else {                            // n == 9: sign from lane9
                    u64 SE = se9p[s];
                    applyG_se(P, C, SE, SE);
                }
            }
            applyF(P, cbs[20 + s], sbs[20 + s], DC2[20 + s], DS2[20 + s]);
        }

        // ---- probs: out index j = t >> 2; reduce over t bits 0,1 + packed halves ----
        u64 acc = 0ULL;
#pragma unroll
        for (int j = 0; j < 8; j++) acc = f2fma(P[j], P[j], acc);
        float alo, ahi; upk(acc, alo, ahi);
        float ssq = alo + ahi;
        ssq += __shfl_xor_sync(0xffffffffu, ssq, 1);
        ssq += __shfl_xor_sync(0xffffffffu, ssq, 2);
        if (!(t & 3)) {
            probs_sm[t >> 2] = ssq;
            out[(b * NSTEP + step) * 64 + (t >> 2)] = ssq;
        }
        __syncthreads();

        // ---- project + normalize; cond_flips cancel across steps ----
        int tj = tIdx[step + 1];
        float invn = 1.0f / sqrtf(probs_sm[tj]);
        if ((t >> 2) == tj) {
            u64 INV = bc(invn);
#pragma unroll
            for (int j = 0; j < 8; j++) P[j] = f2mul(INV, P[j]);
        } else {
#pragma unroll
            for (int j = 0; j < 8; j++) P[j] = 0ULL;
        }
    }

    // ---- second tuple output: measured = inputs[:,1:] as float ----
    if (out_size > 32768 && t < 48) {
        out[32768 + b * 48 + t] = (float)inb[6 + t];
    }
}

} // namespace

extern "C" void kernel_launch(void* const* d_in, const int* in_sizes, int n_in,
                              void* d_out, int out_size) {
    const int*   inputs = nullptr;
    const float* ua     = nullptr;
    const float* nth    = nullptr;
    for (int i = 0; i < n_in; i++) {
        if (in_sizes[i] == 3456)      inputs = (const int*)d_in[i];
        else if (in_sizes[i] == 20)   ua     = (const float*)d_in[i];
        else if (in_sizes[i] == 220)  nth    = (const float*)d_in[i];
    }
    rvqe_kernel<<<64, NTH>>>(inputs, ua, nth, (float*)d_out, out_size);
}